// round 3
// baseline (speedup 1.0000x reference)
#include <cuda_runtime.h>
#include <cuda_bf16.h>

#define NN 50000
#define EE 1600000
#define GG 512
#define FIN 9
#define HH 64
#define NBLK_SCAN ((NN + 1023) / 1024)   // 49

// ---------------- scratch (static device memory; no allocations) ----------------
__device__ int   g_deg [NN];
__device__ int   g_off [NN];
__device__ int   g_cur [NN];
__device__ int   g_bsum[NBLK_SCAN];
__device__ int   g_boff[NBLK_SCAN];
__device__ int   g_csr_src[EE];
__device__ float g_csr_ea [EE];
__device__ __align__(16) float g_h1[NN * HH];
__device__ float g_pi [NN];
__device__ float g_tot[GG];

// ---------------- init: deg = 0, tot = 0 ----------------
__global__ void k_init() {
    int i = blockIdx.x * blockDim.x + threadIdx.x;
    if (i < NN) g_deg[i] = 0;
    if (i < GG) g_tot[i] = 0.0f;
}

// ---------------- histogram of dst ----------------
__global__ void k_hist(const int* __restrict__ ei) {
    int e = blockIdx.x * blockDim.x + threadIdx.x;
    if (e >= EE) return;
    atomicAdd(&g_deg[ei[EE + e]], 1);
}

// ---------------- scan phase 1: per-chunk exclusive scan ----------------
__global__ void k_scan1() {
    __shared__ int wsum[32];
    int tid = threadIdx.x, lane = tid & 31, wid = tid >> 5;
    int i = blockIdx.x * 1024 + tid;
    int v = (i < NN) ? g_deg[i] : 0;
    int x = v;
#pragma unroll
    for (int o = 1; o < 32; o <<= 1) {
        int y = __shfl_up_sync(0xffffffffu, x, o);
        if (lane >= o) x += y;
    }
    if (lane == 31) wsum[wid] = x;
    __syncthreads();
    if (wid == 0) {
        int w = wsum[lane];
#pragma unroll
        for (int o = 1; o < 32; o <<= 1) {
            int y = __shfl_up_sync(0xffffffffu, w, o);
            if (lane >= o) w += y;
        }
        wsum[lane] = w;
    }
    __syncthreads();
    int wp = (wid == 0) ? 0 : wsum[wid - 1];
    if (i < NN) g_off[i] = wp + x - v;          // chunk-local exclusive
    if (tid == 1023) g_bsum[blockIdx.x] = wsum[31];
}

// ---------------- scan phase 2: scan the 49 block sums ----------------
__global__ void k_scan2() {
    __shared__ int s[64];
    int tid = threadIdx.x;
    s[tid] = (tid < NBLK_SCAN) ? g_bsum[tid] : 0;
    __syncthreads();
#pragma unroll
    for (int o = 1; o < 64; o <<= 1) {
        int v = (tid >= o) ? s[tid - o] : 0;
        __syncthreads();
        s[tid] += v;
        __syncthreads();
    }
    if (tid < NBLK_SCAN) g_boff[tid] = (tid == 0) ? 0 : s[tid - 1];
}

// ---------------- scan phase 3: add block offsets, init cursors ----------------
__global__ void k_scan3() {
    int i = blockIdx.x * blockDim.x + threadIdx.x;
    if (i >= NN) return;
    int v = g_off[i] + g_boff[i >> 10];
    g_off[i] = v;
    g_cur[i] = v;
}

// ---------------- scatter edges into CSR (by dst) ----------------
__global__ void k_scatter(const int* __restrict__ ei,
                          const float* __restrict__ ea) {
    int e = blockIdx.x * blockDim.x + threadIdx.x;
    if (e >= EE) return;
    int s = ei[e];
    int d = ei[EE + e];
    int p = atomicAdd(&g_cur[d], 1);
    g_csr_src[p] = s;
    g_csr_ea[p] = ea[e];
}

// ---------------- fused conv1: gather (F=9) + MLP1 -> h1 ----------------
#define NODES_PER_BLK 128
__global__ void __launch_bounds__(256) k_fused1(const float* __restrict__ x,
                       const float* __restrict__ e1w, const float* __restrict__ e1b,
                       const float* __restrict__ w1a, const float* __restrict__ b1a,
                       const float* __restrict__ w1b, const float* __restrict__ b1b) {
    __shared__ float sw1a[HH * FIN];
    __shared__ float sw1bt[HH * HH];     // transposed [k*64+j]
    __shared__ float sb1a[HH], sb1b[HH];
    __shared__ float s_in[4][FIN];
    __shared__ float s_t[4][HH];

    int tid = threadIdx.x;
    for (int i = tid; i < HH * FIN; i += 256) sw1a[i] = w1a[i];
    for (int i = tid; i < HH * HH; i += 256) {
        int jj = i >> 6, kk = i & 63;
        sw1bt[kk * HH + jj] = w1b[i];
    }
    if (tid < HH) { sb1a[tid] = b1a[tid]; sb1b[tid] = b1b[tid]; }

    int j = tid & 63, r = tid >> 6;
    float wv = 0.0f, bv = 0.0f;
    if (j < FIN) { wv = e1w[j]; bv = e1b[j]; }
    __syncthreads();

    int n_base = blockIdx.x * NODES_PER_BLK;
    for (int it = 0; it < NODES_PER_BLK / 4; it++) {
        int n = n_base + it * 4 + r;
        bool valid = (n < NN);

        if (valid && j < FIN) {
            int base = g_off[n], deg = g_deg[n];
            float acc = 0.0f;
            int t = 0;
            for (; t + 4 <= deg; t += 4) {
                int s0 = g_csr_src[base + t + 0];
                int s1 = g_csr_src[base + t + 1];
                int s2 = g_csr_src[base + t + 2];
                int s3 = g_csr_src[base + t + 3];
                float a0 = g_csr_ea[base + t + 0];
                float a1 = g_csr_ea[base + t + 1];
                float a2 = g_csr_ea[base + t + 2];
                float a3 = g_csr_ea[base + t + 3];
                float h0 = x[s0 * FIN + j];
                float h1v = x[s1 * FIN + j];
                float h2 = x[s2 * FIN + j];
                float h3 = x[s3 * FIN + j];
                acc += fmaxf(h0 + a0 * wv + bv, 0.0f);
                acc += fmaxf(h1v + a1 * wv + bv, 0.0f);
                acc += fmaxf(h2 + a2 * wv + bv, 0.0f);
                acc += fmaxf(h3 + a3 * wv + bv, 0.0f);
            }
            for (; t < deg; t++) {
                int s0 = g_csr_src[base + t];
                float a0 = g_csr_ea[base + t];
                acc += fmaxf(x[s0 * FIN + j] + a0 * wv + bv, 0.0f);
            }
            s_in[r][j] = x[n * FIN + j] + acc;
        }
        __syncthreads();

        float tval = 0.0f;
        if (valid) {
            float a1 = sb1a[j];
#pragma unroll
            for (int k = 0; k < FIN; k++) a1 += s_in[r][k] * sw1a[j * FIN + k];
            tval = fmaxf(a1, 0.0f);
        }
        s_t[r][j] = tval;
        __syncthreads();

        if (valid) {
            float a2 = sb1b[j];
#pragma unroll
            for (int k = 0; k < HH; k++) a2 += s_t[r][k] * sw1bt[k * HH + j];
            g_h1[n * HH + j] = fmaxf(a2, 0.0f);
        }
        __syncthreads();
    }
}

// ---------------- fused conv2: gather (F=64) + MLP2 + readout ----------------
__global__ void __launch_bounds__(256) k_fused2(const float* __restrict__ e2w, const float* __restrict__ e2b,
                       const float* __restrict__ w2a, const float* __restrict__ b2a,
                       const float* __restrict__ w2b, const float* __restrict__ b2b,
                       const float* __restrict__ wr1, const float* __restrict__ br1,
                       const float* __restrict__ wr2, const float* __restrict__ br2,
                       const int* __restrict__ batch,
                       const int* __restrict__ tmask,
                       const float* __restrict__ ccost) {
    __shared__ float swa[HH * HH];   // transposed
    __shared__ float swb[HH * HH];   // transposed
    __shared__ float swr[HH * 32];   // transposed [k*32+j]
    __shared__ float sba[HH], sbb[HH], sbr[32], swr2s[32];
    __shared__ float s_in[4][HH];
    __shared__ float s_t[4][HH];
    __shared__ float s_h[4][HH];

    int tid = threadIdx.x;
    for (int i = tid; i < HH * HH; i += 256) {
        int jj = i >> 6, kk = i & 63;
        swa[kk * HH + jj] = w2a[i];
        swb[kk * HH + jj] = w2b[i];
    }
    for (int i = tid; i < 32 * HH; i += 256) {
        int jj = i >> 6, kk = i & 63;           // wr1 [32][64]
        swr[kk * 32 + jj] = wr1[i];
    }
    if (tid < HH) { sba[tid] = b2a[tid]; sbb[tid] = b2b[tid]; }
    if (tid < 32) { sbr[tid] = br1[tid]; swr2s[tid] = wr2[tid]; }

    int j = tid & 63, r = tid >> 6;
    float wv = e2w[j], bv = e2b[j];
    __syncthreads();

    int n_base = blockIdx.x * NODES_PER_BLK;
    for (int it = 0; it < NODES_PER_BLK / 4; it++) {
        int n = n_base + it * 4 + r;
        bool valid = (n < NN);

        if (valid) {
            int base = g_off[n], deg = g_deg[n];
            float acc = 0.0f;
            int t = 0;
            for (; t + 4 <= deg; t += 4) {
                int s0 = g_csr_src[base + t + 0];
                int s1 = g_csr_src[base + t + 1];
                int s2 = g_csr_src[base + t + 2];
                int s3 = g_csr_src[base + t + 3];
                float a0 = g_csr_ea[base + t + 0];
                float a1 = g_csr_ea[base + t + 1];
                float a2 = g_csr_ea[base + t + 2];
                float a3 = g_csr_ea[base + t + 3];
                float h0 = g_h1[s0 * HH + j];
                float h1v = g_h1[s1 * HH + j];
                float h2 = g_h1[s2 * HH + j];
                float h3 = g_h1[s3 * HH + j];
                acc += fmaxf(h0 + a0 * wv + bv, 0.0f);
                acc += fmaxf(h1v + a1 * wv + bv, 0.0f);
                acc += fmaxf(h2 + a2 * wv + bv, 0.0f);
                acc += fmaxf(h3 + a3 * wv + bv, 0.0f);
            }
            for (; t < deg; t++) {
                int s0 = g_csr_src[base + t];
                float a0 = g_csr_ea[base + t];
                acc += fmaxf(g_h1[s0 * HH + j] + a0 * wv + bv, 0.0f);
            }
            s_in[r][j] = g_h1[n * HH + j] + acc;
        }
        __syncthreads();

        float tval = 0.0f;
        if (valid) {
            float a1 = sba[j];
#pragma unroll
            for (int k = 0; k < HH; k++) a1 += s_in[r][k] * swa[k * HH + j];
            tval = fmaxf(a1, 0.0f);
        }
        s_t[r][j] = tval;
        __syncthreads();

        float hval = 0.0f;
        if (valid) {
            float a2 = sbb[j];
#pragma unroll
            for (int k = 0; k < HH; k++) a2 += s_t[r][k] * swb[k * HH + j];
            hval = fmaxf(a2, 0.0f);
        }
        s_h[r][j] = hval;
        __syncthreads();

        // readout: first warp of pair r (lanes j<32) reduces node r
        if (valid && j < 32) {
            float a3 = sbr[j];
#pragma unroll
            for (int k = 0; k < HH; k++) a3 += s_h[r][k] * swr[k * 32 + j];
            float z = fmaxf(a3, 0.0f) * swr2s[j];
#pragma unroll
            for (int off = 16; off; off >>= 1) z += __shfl_down_sync(0xffffffffu, z, off);
            if (j == 0) {
                z += br2[0];
                float pi = 1.0f / (1.0f + __expf(-z));
                pi *= (1.0f - (float)tmask[n]);
                g_pi[n] = pi;
                atomicAdd(&g_tot[batch[n]], pi * ccost[n]);
            }
        }
        __syncthreads();
    }
}

// ---------------- final: out = pi * min(B/(tot+eps), 1) ----------------
__global__ void k_final(const int* __restrict__ batch,
                        const float* __restrict__ Bt,
                        float* __restrict__ out) {
    int i = blockIdx.x * blockDim.x + threadIdx.x;
    if (i >= NN) return;
    int b = batch[i];
    float ratio = fminf(Bt[b] / (g_tot[b] + 1e-12f), 1.0f);
    out[i] = g_pi[i] * ratio;
}

extern "C" void kernel_launch(void* const* d_in, const int* in_sizes, int n_in,
                              void* d_out, int out_size) {
    const float* x      = (const float*)d_in[0];
    const int*   ei     = (const int*)d_in[1];
    const float* ea     = (const float*)d_in[2];
    const int*   batch  = (const int*)d_in[3];
    const float* Btot   = (const float*)d_in[4];
    const int*   tmask  = (const int*)d_in[5];
    const float* ccost  = (const float*)d_in[6];
    const float* e1w    = (const float*)d_in[7];
    const float* e1b    = (const float*)d_in[8];
    const float* w1a    = (const float*)d_in[9];
    const float* b1a    = (const float*)d_in[10];
    const float* w1b    = (const float*)d_in[11];
    const float* b1b    = (const float*)d_in[12];
    const float* e2w    = (const float*)d_in[13];
    const float* e2b    = (const float*)d_in[14];
    const float* w2a    = (const float*)d_in[15];
    const float* b2a    = (const float*)d_in[16];
    const float* w2b    = (const float*)d_in[17];
    const float* b2b    = (const float*)d_in[18];
    const float* wr1    = (const float*)d_in[19];
    const float* br1    = (const float*)d_in[20];
    const float* wr2    = (const float*)d_in[21];
    const float* br2    = (const float*)d_in[22];
    float* out = (float*)d_out;

    k_init<<<(NN + 255) / 256, 256>>>();
    k_hist<<<(EE + 255) / 256, 256>>>(ei);
    k_scan1<<<NBLK_SCAN, 1024>>>();
    k_scan2<<<1, 64>>>();
    k_scan3<<<(NN + 255) / 256, 256>>>();
    k_scatter<<<(EE + 255) / 256, 256>>>(ei, ea);
    int nblk = (NN + NODES_PER_BLK - 1) / NODES_PER_BLK;
    k_fused1<<<nblk, 256>>>(x, e1w, e1b, w1a, b1a, w1b, b1b);
    k_fused2<<<nblk, 256>>>(e2w, e2b, w2a, b2a, w2b, b2b,
                            wr1, br1, wr2, br2, batch, tmask, ccost);
    k_final<<<(NN + 255) / 256, 256>>>(batch, Btot, out);
}

// round 4
// speedup vs baseline: 1.3894x; 1.3894x over previous
#include <cuda_runtime.h>
#include <cuda_bf16.h>

#define NN 50000
#define EE 1600000
#define GG 512
#define FIN 9
#define HH 64
#define NBLK_SCAN ((NN + 1023) / 1024)   // 49
#define FULL 0xffffffffu

// ---------------- scratch (static device memory; no allocations) ----------------
__device__ int   g_deg [NN];
__device__ int   g_off [NN];
__device__ int   g_cur [NN];
__device__ int   g_bsum[NBLK_SCAN];
__device__ int   g_boff[NBLK_SCAN];
__device__ __align__(16) int2  g_csr[EE];      // packed {src, __float_as_int(ea)}
__device__ __align__(16) float g_h1[NN * HH];
__device__ float g_pi [NN];
__device__ float g_tot[GG];

// ---------------- init: deg = 0, tot = 0 ----------------
__global__ void k_init() {
    int i = blockIdx.x * blockDim.x + threadIdx.x;
    if (i < NN) g_deg[i] = 0;
    if (i < GG) g_tot[i] = 0.0f;
}

// ---------------- histogram of dst ----------------
__global__ void k_hist(const int* __restrict__ ei) {
    int e = blockIdx.x * blockDim.x + threadIdx.x;
    if (e >= EE) return;
    atomicAdd(&g_deg[ei[EE + e]], 1);
}

// ---------------- scan phase 1: per-chunk exclusive scan ----------------
__global__ void k_scan1() {
    __shared__ int wsum[32];
    int tid = threadIdx.x, lane = tid & 31, wid = tid >> 5;
    int i = blockIdx.x * 1024 + tid;
    int v = (i < NN) ? g_deg[i] : 0;
    int x = v;
#pragma unroll
    for (int o = 1; o < 32; o <<= 1) {
        int y = __shfl_up_sync(FULL, x, o);
        if (lane >= o) x += y;
    }
    if (lane == 31) wsum[wid] = x;
    __syncthreads();
    if (wid == 0) {
        int w = wsum[lane];
#pragma unroll
        for (int o = 1; o < 32; o <<= 1) {
            int y = __shfl_up_sync(FULL, w, o);
            if (lane >= o) w += y;
        }
        wsum[lane] = w;
    }
    __syncthreads();
    int wp = (wid == 0) ? 0 : wsum[wid - 1];
    if (i < NN) g_off[i] = wp + x - v;
    if (tid == 1023) g_bsum[blockIdx.x] = wsum[31];
}

// ---------------- scan phase 2 ----------------
__global__ void k_scan2() {
    __shared__ int s[64];
    int tid = threadIdx.x;
    s[tid] = (tid < NBLK_SCAN) ? g_bsum[tid] : 0;
    __syncthreads();
#pragma unroll
    for (int o = 1; o < 64; o <<= 1) {
        int v = (tid >= o) ? s[tid - o] : 0;
        __syncthreads();
        s[tid] += v;
        __syncthreads();
    }
    if (tid < NBLK_SCAN) g_boff[tid] = (tid == 0) ? 0 : s[tid - 1];
}

// ---------------- scan phase 3 ----------------
__global__ void k_scan3() {
    int i = blockIdx.x * blockDim.x + threadIdx.x;
    if (i >= NN) return;
    int v = g_off[i] + g_boff[i >> 10];
    g_off[i] = v;
    g_cur[i] = v;
}

// ---------------- scatter edges into packed CSR (by dst) ----------------
__global__ void k_scatter(const int* __restrict__ ei,
                          const float* __restrict__ ea) {
    int e = blockIdx.x * blockDim.x + threadIdx.x;
    if (e >= EE) return;
    int s = ei[e];
    int d = ei[EE + e];
    int p = atomicAdd(&g_cur[d], 1);
    g_csr[p] = make_int2(s, __float_as_int(ea[e]));
}

// ================= fused conv1: gather (F=9) + MLP1 -> h1 =================
#define NODES_PER_BLK 128
#define TILE 32

__global__ void __launch_bounds__(256) k_fused1(const float* __restrict__ x,
                       const float* __restrict__ e1w, const float* __restrict__ e1b,
                       const float* __restrict__ w1a, const float* __restrict__ b1a,
                       const float* __restrict__ w1b, const float* __restrict__ b1b) {
    __shared__ float sw1a[HH * FIN];      // [j*9+k]
    __shared__ float sw1bt[HH * HH];      // transposed [k*64+j]
    __shared__ float sb1a[HH], sb1b[HH];
    __shared__ float s_agg[TILE][FIN];
    __shared__ float s_t[TILE][HH];

    int tid = threadIdx.x, lane = tid & 31, warp = tid >> 5;
    for (int i = tid; i < HH * FIN; i += 256) sw1a[i] = w1a[i];
    for (int i = tid; i < HH * HH; i += 256) {
        int jj = i >> 6, kk = i & 63;
        sw1bt[kk * HH + jj] = w1b[i];
    }
    if (tid < HH) { sb1a[tid] = b1a[tid]; sb1b[tid] = b1b[tid]; }

    float wv = 0.0f, bv = 0.0f;
    if (lane < FIN) { wv = e1w[lane]; bv = e1b[lane]; }
    __syncthreads();

    int n_base = blockIdx.x * NODES_PER_BLK;
    for (int tile = 0; tile < NODES_PER_BLK / TILE; tile++) {
        int tbase = n_base + tile * TILE;

        // ---- gather phase: warp w handles nodes tbase + w*4 .. +3 ----
        for (int q = 0; q < 4; q++) {
            int nl = warp * 4 + q;
            int n = tbase + nl;
            if (n < NN) {
                int base = g_off[n], deg = g_deg[n];
                float acc = 0.0f;
                for (int c = 0; c < deg; c += 32) {
                    int cnt = min(deg - c, 32);
                    int2 p = (lane < cnt) ? g_csr[base + c + lane] : make_int2(0, 0);
                    if (cnt == 32) {
#pragma unroll
                        for (int k = 0; k < 32; k++) {
                            int s = __shfl_sync(FULL, p.x, k);
                            float a = __int_as_float(__shfl_sync(FULL, p.y, k));
                            float xv = (lane < FIN) ? x[s * FIN + lane] : 0.0f;
                            acc += fmaxf(xv + a * wv + bv, 0.0f);
                        }
                    } else {
                        for (int k = 0; k < cnt; k++) {
                            int s = __shfl_sync(FULL, p.x, k);
                            float a = __int_as_float(__shfl_sync(FULL, p.y, k));
                            float xv = (lane < FIN) ? x[s * FIN + lane] : 0.0f;
                            acc += fmaxf(xv + a * wv + bv, 0.0f);
                        }
                    }
                }
                if (lane < FIN) s_agg[nl][lane] = x[n * FIN + lane] + acc;
            }
        }
        __syncthreads();

        // ---- MLP stage 1: 9 -> 64, all 32 nodes (8 groups of 4) ----
        int j = tid & 63, r = tid >> 6;
#pragma unroll
        for (int g = 0; g < TILE / 4; g++) {
            int nl = g * 4 + r;
            float a1 = sb1a[j];
#pragma unroll
            for (int k = 0; k < FIN; k++) a1 += s_agg[nl][k] * sw1a[j * FIN + k];
            s_t[nl][j] = fmaxf(a1, 0.0f);
        }
        __syncthreads();

        // ---- MLP stage 2: 64 -> 64, write h1 ----
#pragma unroll
        for (int g = 0; g < TILE / 4; g++) {
            int nl = g * 4 + r;
            int n = tbase + nl;
            if (n < NN) {
                float a2 = sb1b[j];
#pragma unroll
                for (int k = 0; k < HH; k++) a2 += s_t[nl][k] * sw1bt[k * HH + j];
                g_h1[n * HH + j] = fmaxf(a2, 0.0f);
            }
        }
        __syncthreads();
    }
}

// ================= fused conv2: gather (F=64) + MLP2 + readout =================
__global__ void __launch_bounds__(256) k_fused2(const float* __restrict__ e2w, const float* __restrict__ e2b,
                       const float* __restrict__ w2a, const float* __restrict__ b2a,
                       const float* __restrict__ w2b, const float* __restrict__ b2b,
                       const float* __restrict__ wr1, const float* __restrict__ br1,
                       const float* __restrict__ wr2, const float* __restrict__ br2,
                       const int* __restrict__ batch,
                       const int* __restrict__ tmask,
                       const float* __restrict__ ccost) {
    __shared__ float swa[HH * HH];    // transposed [k*64+j]
    __shared__ float swb[HH * HH];    // transposed
    __shared__ float swr[HH * 32];    // transposed [k*32+j]
    __shared__ float sba[HH], sbb[HH], sbr[32], swr2s[32];
    __shared__ float s_agg[TILE][HH];
    __shared__ float s_t[TILE][HH];
    __shared__ float s_h[TILE][HH];

    int tid = threadIdx.x, lane = tid & 31, warp = tid >> 5;
    for (int i = tid; i < HH * HH; i += 256) {
        int jj = i >> 6, kk = i & 63;
        swa[kk * HH + jj] = w2a[i];
        swb[kk * HH + jj] = w2b[i];
    }
    for (int i = tid; i < 32 * HH; i += 256) {
        int jj = i >> 6, kk = i & 63;            // wr1 [32][64]
        swr[kk * 32 + jj] = wr1[i];
    }
    if (tid < HH) { sba[tid] = b2a[tid]; sbb[tid] = b2b[tid]; }
    if (tid < 32) { sbr[tid] = br1[tid]; swr2s[tid] = wr2[tid]; }

    const float2* h1f2 = reinterpret_cast<const float2*>(g_h1);
    float2 wv = reinterpret_cast<const float2*>(e2w)[lane];
    float2 bv = reinterpret_cast<const float2*>(e2b)[lane];
    __syncthreads();

    int n_base = blockIdx.x * NODES_PER_BLK;
    for (int tile = 0; tile < NODES_PER_BLK / TILE; tile++) {
        int tbase = n_base + tile * TILE;

        // ---- gather phase: warp w handles nodes tbase + w*4 .. +3 ----
        for (int q = 0; q < 4; q++) {
            int nl = warp * 4 + q;
            int n = tbase + nl;
            if (n < NN) {
                int base = g_off[n], deg = g_deg[n];
                float2 acc = make_float2(0.0f, 0.0f);
                for (int c = 0; c < deg; c += 32) {
                    int cnt = min(deg - c, 32);
                    int2 p = (lane < cnt) ? g_csr[base + c + lane] : make_int2(0, 0);
                    if (cnt == 32) {
#pragma unroll
                        for (int k = 0; k < 32; k++) {
                            int s = __shfl_sync(FULL, p.x, k);
                            float a = __int_as_float(__shfl_sync(FULL, p.y, k));
                            float2 h = h1f2[s * 32 + lane];
                            acc.x += fmaxf(h.x + a * wv.x + bv.x, 0.0f);
                            acc.y += fmaxf(h.y + a * wv.y + bv.y, 0.0f);
                        }
                    } else {
                        for (int k = 0; k < cnt; k++) {
                            int s = __shfl_sync(FULL, p.x, k);
                            float a = __int_as_float(__shfl_sync(FULL, p.y, k));
                            float2 h = h1f2[s * 32 + lane];
                            acc.x += fmaxf(h.x + a * wv.x + bv.x, 0.0f);
                            acc.y += fmaxf(h.y + a * wv.y + bv.y, 0.0f);
                        }
                    }
                }
                float2 hs = h1f2[n * 32 + lane];
                acc.x += hs.x;
                acc.y += hs.y;
                *reinterpret_cast<float2*>(&s_agg[nl][2 * lane]) = acc;
            }
        }
        __syncthreads();

        // ---- MLP stage 1: 64 -> 64, all 32 nodes ----
        int j = tid & 63, r = tid >> 6;
#pragma unroll
        for (int g = 0; g < TILE / 4; g++) {
            int nl = g * 4 + r;
            float a1 = sba[j];
#pragma unroll
            for (int k = 0; k < HH; k++) a1 += s_agg[nl][k] * swa[k * HH + j];
            s_t[nl][j] = fmaxf(a1, 0.0f);
        }
        __syncthreads();

        // ---- MLP stage 2: 64 -> 64 ----
#pragma unroll
        for (int g = 0; g < TILE / 4; g++) {
            int nl = g * 4 + r;
            float a2 = sbb[j];
#pragma unroll
            for (int k = 0; k < HH; k++) a2 += s_t[nl][k] * swb[k * HH + j];
            s_h[nl][j] = fmaxf(a2, 0.0f);
        }
        __syncthreads();

        // ---- readout: warp w reduces nodes w*4 .. w*4+3 ----
        for (int q = 0; q < 4; q++) {
            int nl = warp * 4 + q;
            int n = tbase + nl;
            if (n < NN) {
                float a3 = sbr[lane];
#pragma unroll
                for (int k = 0; k < HH; k++) a3 += s_h[nl][k] * swr[k * 32 + lane];
                float z = fmaxf(a3, 0.0f) * swr2s[lane];
#pragma unroll
                for (int off = 16; off; off >>= 1) z += __shfl_down_sync(FULL, z, off);
                if (lane == 0) {
                    z += br2[0];
                    float pi = 1.0f / (1.0f + __expf(-z));
                    pi *= (1.0f - (float)tmask[n]);
                    g_pi[n] = pi;
                    atomicAdd(&g_tot[batch[n]], pi * ccost[n]);
                }
            }
        }
        __syncthreads();
    }
}

// ---------------- final: out = pi * min(B/(tot+eps), 1) ----------------
__global__ void k_final(const int* __restrict__ batch,
                        const float* __restrict__ Bt,
                        float* __restrict__ out) {
    int i = blockIdx.x * blockDim.x + threadIdx.x;
    if (i >= NN) return;
    int b = batch[i];
    float ratio = fminf(Bt[b] / (g_tot[b] + 1e-12f), 1.0f);
    out[i] = g_pi[i] * ratio;
}

extern "C" void kernel_launch(void* const* d_in, const int* in_sizes, int n_in,
                              void* d_out, int out_size) {
    const float* x      = (const float*)d_in[0];
    const int*   ei     = (const int*)d_in[1];
    const float* ea     = (const float*)d_in[2];
    const int*   batch  = (const int*)d_in[3];
    const float* Btot   = (const float*)d_in[4];
    const int*   tmask  = (const int*)d_in[5];
    const float* ccost  = (const float*)d_in[6];
    const float* e1w    = (const float*)d_in[7];
    const float* e1b    = (const float*)d_in[8];
    const float* w1a    = (const float*)d_in[9];
    const float* b1a    = (const float*)d_in[10];
    const float* w1b    = (const float*)d_in[11];
    const float* b1b    = (const float*)d_in[12];
    const float* e2w    = (const float*)d_in[13];
    const float* e2b    = (const float*)d_in[14];
    const float* w2a    = (const float*)d_in[15];
    const float* b2a    = (const float*)d_in[16];
    const float* w2b    = (const float*)d_in[17];
    const float* b2b    = (const float*)d_in[18];
    const float* wr1    = (const float*)d_in[19];
    const float* br1    = (const float*)d_in[20];
    const float* wr2    = (const float*)d_in[21];
    const float* br2    = (const float*)d_in[22];
    float* out = (float*)d_out;

    k_init<<<(NN + 255) / 256, 256>>>();
    k_hist<<<(EE + 255) / 256, 256>>>(ei);
    k_scan1<<<NBLK_SCAN, 1024>>>();
    k_scan2<<<1, 64>>>();
    k_scan3<<<(NN + 255) / 256, 256>>>();
    k_scatter<<<(EE + 255) / 256, 256>>>(ei, ea);
    int nblk = (NN + NODES_PER_BLK - 1) / NODES_PER_BLK;
    k_fused1<<<nblk, 256>>>(x, e1w, e1b, w1a, b1a, w1b, b1b);
    k_fused2<<<nblk, 256>>>(e2w, e2b, w2a, b2a, w2b, b2b,
                            wr1, br1, wr2, br2, batch, tmask, ccost);
    k_final<<<(NN + 255) / 256, 256>>>(batch, Btot, out);
}

// round 6
// speedup vs baseline: 2.0726x; 1.4917x over previous
#include <cuda_runtime.h>
#include <cuda_bf16.h>

#define NN 50000
#define EE 1600000
#define GG 512
#define FIN 9
#define HH 64
#define NBLK_SCAN ((NN + 1023) / 1024)   // 49
#define FULL 0xffffffffu
#define NPB 128                          // nodes per block in MLP kernels

// ---------------- scratch (static device memory; no allocations) ----------------
__device__ int   g_deg [NN];
__device__ int   g_off [NN];
__device__ int   g_cur [NN];
__device__ int   g_bsum[NBLK_SCAN];
__device__ __align__(16) int2  g_csr[EE];          // packed {src, ea bits}
__device__ __align__(16) float g_agg1[NN * FIN];
__device__ __align__(16) float g_h1  [NN * HH];    // h1, later overwritten with h2
__device__ __align__(16) float g_agg2[NN * HH];
__device__ float g_pi [NN];
__device__ float g_tot[GG];
// pre-transposed weights
__device__ float g_w1a_t[FIN * HH];
__device__ float g_w1b_t[HH * HH];
__device__ float g_w2a_t[HH * HH];
__device__ float g_w2b_t[HH * HH];
__device__ float g_wr1_t[HH * 32];

// ---------------- init ----------------
__global__ void k_init() {
    int i = blockIdx.x * blockDim.x + threadIdx.x;
    if (i < NN) g_deg[i] = 0;
    if (i < GG) g_tot[i] = 0.0f;
}

// ---------------- weight transpose (once per call, tiny) ----------------
__global__ void k_prep(const float* __restrict__ w1a, const float* __restrict__ w1b,
                       const float* __restrict__ w2a, const float* __restrict__ w2b,
                       const float* __restrict__ wr1) {
    int i = blockIdx.x * 256 + threadIdx.x;
    if (i < FIN * HH) { int k = i >> 6, j = i & 63; g_w1a_t[i] = w1a[j * FIN + k]; }
    if (i < HH * HH) {
        int k = i >> 6, j = i & 63;
        g_w1b_t[i] = w1b[j * HH + k];
        g_w2a_t[i] = w2a[j * HH + k];
        g_w2b_t[i] = w2b[j * HH + k];
    }
    if (i < HH * 32) { int k = i >> 5, j = i & 31; g_wr1_t[i] = wr1[j * HH + k]; }
}

// ---------------- histogram of dst ----------------
__global__ void k_hist(const int* __restrict__ ei) {
    int e = blockIdx.x * blockDim.x + threadIdx.x;
    if (e >= EE) return;
    atomicAdd(&g_deg[ei[EE + e]], 1);
}

// ---------------- scan phase 1: per-1024-chunk exclusive scan ----------------
__global__ void k_scan1() {
    __shared__ int wsum[32];
    int tid = threadIdx.x, lane = tid & 31, wid = tid >> 5;
    int i = blockIdx.x * 1024 + tid;
    int v = (i < NN) ? g_deg[i] : 0;
    int x = v;
#pragma unroll
    for (int o = 1; o < 32; o <<= 1) {
        int y = __shfl_up_sync(FULL, x, o);
        if (lane >= o) x += y;
    }
    if (lane == 31) wsum[wid] = x;
    __syncthreads();
    if (wid == 0) {
        int w = wsum[lane];
#pragma unroll
        for (int o = 1; o < 32; o <<= 1) {
            int y = __shfl_up_sync(FULL, w, o);
            if (lane >= o) w += y;
        }
        wsum[lane] = w;
    }
    __syncthreads();
    int wp = (wid == 0) ? 0 : wsum[wid - 1];
    if (i < NN) g_off[i] = wp + x - v;
    if (tid == 1023) g_bsum[blockIdx.x] = wsum[31];
}

// ---------------- scan phases 2+3 merged ----------------
__global__ void k_scan23() {
    __shared__ int sb[64];
    int tid = threadIdx.x;
    if (tid < 64) sb[tid] = (tid < NBLK_SCAN) ? g_bsum[tid] : 0;
    __syncthreads();
    if (tid == 0) {
        int run = 0;
        for (int j = 0; j < NBLK_SCAN; j++) { int t = sb[j]; sb[j] = run; run += t; }
    }
    __syncthreads();
    int i = blockIdx.x * blockDim.x + tid;
    if (i < NN) {
        int v = g_off[i] + sb[i >> 10];
        g_off[i] = v;
        g_cur[i] = v;
    }
}

// ---------------- scatter edges into packed CSR (by dst) ----------------
__global__ void k_scatter(const int* __restrict__ ei,
                          const float* __restrict__ ea) {
    int e = blockIdx.x * blockDim.x + threadIdx.x;
    if (e >= EE) return;
    int s = ei[e];
    int d = ei[EE + e];
    int p = atomicAdd(&g_cur[d], 1);
    g_csr[p] = make_int2(s, __float_as_int(ea[e]));
}

// ================= gather1: warp-per-node, 3 edges/step (F=9) =================
__global__ void __launch_bounds__(256) k_gather1(const float* __restrict__ x,
                        const float* __restrict__ e1w, const float* __restrict__ e1b) {
    __shared__ int2 s_edge[8][32];
    int lane = threadIdx.x & 31, w = threadIdx.x >> 5;
    int n = blockIdx.x * 8 + w;
    if (n >= NN) return;

    int eoff = lane / FIN;               // 0..2 for lanes 0..26, 3 for 27..31
    int f = lane - eoff * FIN;
    bool act = (lane < 27);
    float wv = act ? e1w[f] : 0.0f;
    float bv = act ? e1b[f] : 0.0f;

    int base = g_off[n], deg = g_deg[n];
    float acc = 0.0f;
    for (int c = 0; c < deg; c += 32) {
        int cnt = min(deg - c, 32);
        if (lane < cnt) s_edge[w][lane] = g_csr[base + c + lane];
        __syncwarp();
        if (cnt == 32) {
#pragma unroll
            for (int t = 0; t < 11; t++) {
                int idx = 3 * t + eoff;
                if (act && idx < 32) {
                    int2 e = s_edge[w][idx];
                    float a = __int_as_float(e.y);
                    float xv = x[e.x * FIN + f];
                    acc += fmaxf(xv + a * wv + bv, 0.0f);
                }
            }
        } else {
            int steps = (cnt + 2) / 3;
            for (int t = 0; t < steps; t++) {
                int idx = 3 * t + eoff;
                if (act && idx < cnt) {
                    int2 e = s_edge[w][idx];
                    float a = __int_as_float(e.y);
                    float xv = x[e.x * FIN + f];
                    acc += fmaxf(xv + a * wv + bv, 0.0f);
                }
            }
        }
        __syncwarp();
    }
    float v1 = __shfl_down_sync(FULL, acc, 9);
    float v2 = __shfl_down_sync(FULL, acc, 18);
    if (lane < FIN) g_agg1[n * FIN + lane] = x[n * FIN + lane] + acc + v1 + v2;
}

// ================= mlp1: (9->64 relu)->(64->64 relu) -> g_h1 =================
__global__ void __launch_bounds__(256) k_mlp1(const float* __restrict__ b1a,
                                              const float* __restrict__ b1b) {
    __shared__ float swa_t[FIN * HH];     // [k][j]
    __shared__ float swb_t[HH * HH];      // [k][j]
    __shared__ float sba[HH], sbb[HH];
    __shared__ float s_in[32][FIN];
    __shared__ float s_t[32][HH];

    int tid = threadIdx.x, lane = tid & 31, w = tid >> 5;
    for (int i = tid; i < FIN * HH; i += 256) swa_t[i] = g_w1a_t[i];
    for (int i = tid; i < HH * HH; i += 256) swb_t[i] = g_w1b_t[i];
    if (tid < HH) { sba[tid] = b1a[tid]; sbb[tid] = b1b[tid]; }
    __syncthreads();

    for (int tile = 0; tile < NPB / 32; tile++) {
        int tbase = blockIdx.x * NPB + tile * 32;
        for (int i = tid; i < 32 * FIN; i += 256) {
            int nl = i / FIN, k = i - nl * FIN;
            int nn2 = tbase + nl;
            s_in[nl][k] = (nn2 < NN) ? g_agg1[nn2 * FIN + k] : 0.0f;
        }
        __syncthreads();

        // stage1: warp w handles nodes q*8+w; lane computes outputs (2*lane, 2*lane+1)
#pragma unroll
        for (int q = 0; q < 4; q++) {
            int nl = q * 8 + w;
            float2 acc = make_float2(sba[2 * lane], sba[2 * lane + 1]);
#pragma unroll
            for (int k = 0; k < FIN; k++) {
                float av = s_in[nl][k];
                float2 wt = ((const float2*)(swa_t + k * HH))[lane];
                acc.x += av * wt.x;
                acc.y += av * wt.y;
            }
            acc.x = fmaxf(acc.x, 0.0f);
            acc.y = fmaxf(acc.y, 0.0f);
            *(float2*)&s_t[nl][2 * lane] = acc;
        }
        __syncthreads();

        // stage2: 64->64 -> g_h1
#pragma unroll
        for (int q = 0; q < 4; q++) {
            int nl = q * 8 + w;
            int nn2 = tbase + nl;
            float2 acc = make_float2(sbb[2 * lane], sbb[2 * lane + 1]);
#pragma unroll
            for (int k = 0; k < HH; k++) {
                float av = s_t[nl][k];
                float2 wt = ((const float2*)(swb_t + k * HH))[lane];
                acc.x += av * wt.x;
                acc.y += av * wt.y;
            }
            if (nn2 < NN) {
                acc.x = fmaxf(acc.x, 0.0f);
                acc.y = fmaxf(acc.y, 0.0f);
                ((float2*)g_h1)[nn2 * 32 + lane] = acc;
            }
        }
        __syncthreads();
    }
}

// ================= gather2: warp-per-node (F=64), batched loads =================
__global__ void __launch_bounds__(256) k_gather2(const float* __restrict__ e2w,
                                                 const float* __restrict__ e2b) {
    __shared__ int2 s_edge[8][32];
    int lane = threadIdx.x & 31, w = threadIdx.x >> 5;
    int n = blockIdx.x * 8 + w;
    if (n >= NN) return;

    float2 wv = ((const float2*)e2w)[lane];
    float2 bv = ((const float2*)e2b)[lane];
    const float2* h1f2 = (const float2*)g_h1;

    int base = g_off[n], deg = g_deg[n];
    float2 acc = h1f2[n * 32 + lane];     // self term
    for (int c = 0; c < deg; c += 32) {
        int cnt = min(deg - c, 32);
        if (lane < cnt) s_edge[w][lane] = g_csr[base + c + lane];
        __syncwarp();
        if (cnt == 32) {
#pragma unroll
            for (int kb = 0; kb < 4; kb++) {
                float2 h[8]; float a[8];
#pragma unroll
                for (int u = 0; u < 8; u++) {
                    int2 e = s_edge[w][kb * 8 + u];
                    a[u] = __int_as_float(e.y);
                    h[u] = h1f2[e.x * 32 + lane];
                }
#pragma unroll
                for (int u = 0; u < 8; u++) {
                    acc.x += fmaxf(h[u].x + a[u] * wv.x + bv.x, 0.0f);
                    acc.y += fmaxf(h[u].y + a[u] * wv.y + bv.y, 0.0f);
                }
            }
        } else {
            for (int k = 0; k < cnt; k++) {
                int2 e = s_edge[w][k];
                float a = __int_as_float(e.y);
                float2 h = h1f2[e.x * 32 + lane];
                acc.x += fmaxf(h.x + a * wv.x + bv.x, 0.0f);
                acc.y += fmaxf(h.y + a * wv.y + bv.y, 0.0f);
            }
        }
        __syncwarp();
    }
    ((float2*)g_agg2)[n * 32 + lane] = acc;
}

// ================= mlp2: (64->64 relu)x2 -> h2 into g_h1 =================
__global__ void __launch_bounds__(256) k_mlp2(const float* __restrict__ b2a,
                                              const float* __restrict__ b2b) {
    __shared__ float swa_t[HH * HH];
    __shared__ float swb_t[HH * HH];
    __shared__ float s_io0[32][HH];
    __shared__ float s_io1[32][HH];

    int tid = threadIdx.x, lane = tid & 31, w = tid >> 5;
    for (int i = tid; i < HH * HH; i += 256) {
        swa_t[i] = g_w2a_t[i];
        swb_t[i] = g_w2b_t[i];
    }
    const float2* ba = (const float2*)b2a;
    const float2* bb = (const float2*)b2b;
    __syncthreads();

    for (int tile = 0; tile < NPB / 32; tile++) {
        int tbase = blockIdx.x * NPB + tile * 32;
        for (int i = tid; i < 32 * HH; i += 256) {
            int nl = i >> 6, k = i & 63;
            int nn2 = tbase + nl;
            s_io0[nl][k] = (nn2 < NN) ? g_agg2[nn2 * HH + k] : 0.0f;
        }
        __syncthreads();

#pragma unroll
        for (int q = 0; q < 4; q++) {
            int nl = q * 8 + w;
            float2 acc = ba[lane];
#pragma unroll
            for (int k = 0; k < HH; k++) {
                float av = s_io0[nl][k];
                float2 wt = ((const float2*)(swa_t + k * HH))[lane];
                acc.x += av * wt.x;
                acc.y += av * wt.y;
            }
            acc.x = fmaxf(acc.x, 0.0f);
            acc.y = fmaxf(acc.y, 0.0f);
            *(float2*)&s_io1[nl][2 * lane] = acc;
        }
        __syncthreads();

#pragma unroll
        for (int q = 0; q < 4; q++) {
            int nl = q * 8 + w;
            int nn2 = tbase + nl;
            float2 acc = bb[lane];
#pragma unroll
            for (int k = 0; k < HH; k++) {
                float av = s_io1[nl][k];
                float2 wt = ((const float2*)(swb_t + k * HH))[lane];
                acc.x += av * wt.x;
                acc.y += av * wt.y;
            }
            if (nn2 < NN) {
                acc.x = fmaxf(acc.x, 0.0f);
                acc.y = fmaxf(acc.y, 0.0f);
                ((float2*)g_h1)[nn2 * 32 + lane] = acc;   // h2 overwrites h1
            }
        }
        __syncthreads();
    }
}

// ================= readout: pi + per-graph expense =================
__global__ void __launch_bounds__(256) k_readout(const float* __restrict__ br1,
                        const float* __restrict__ wr2, const float* __restrict__ br2,
                        const int* __restrict__ batch,
                        const int* __restrict__ tmask,
                        const float* __restrict__ ccost) {
    __shared__ float swr_t[HH * 32];
    __shared__ float sbr[32], swr2s[32];
    int tid = threadIdx.x, lane = tid & 31, w = tid >> 5;
    for (int i = tid; i < HH * 32; i += 256) swr_t[i] = g_wr1_t[i];
    if (tid < 32) { sbr[tid] = br1[tid]; swr2s[tid] = wr2[tid]; }
    __syncthreads();

    const float2* h2 = (const float2*)g_h1;
    for (int n = blockIdx.x * 8 + w; n < NN; n += gridDim.x * 8) {
        float2 h = h2[n * 32 + lane];
        float a3 = sbr[lane];
#pragma unroll
        for (int k = 0; k < HH; k += 2) {
            float h0 = __shfl_sync(FULL, h.x, k >> 1);
            float h1v = __shfl_sync(FULL, h.y, k >> 1);
            a3 = fmaf(h0, swr_t[k * 32 + lane], a3);
            a3 = fmaf(h1v, swr_t[(k + 1) * 32 + lane], a3);
        }
        float z = fmaxf(a3, 0.0f) * swr2s[lane];
#pragma unroll
        for (int off = 16; off; off >>= 1) z += __shfl_down_sync(FULL, z, off);
        if (lane == 0) {
            z += br2[0];
            float pi = 1.0f / (1.0f + __expf(-z));
            pi *= (1.0f - (float)tmask[n]);
            g_pi[n] = pi;
            atomicAdd(&g_tot[batch[n]], pi * ccost[n]);
        }
    }
}

// ---------------- final ----------------
__global__ void k_final(const int* __restrict__ batch,
                        const float* __restrict__ Bt,
                        float* __restrict__ out) {
    int i = blockIdx.x * blockDim.x + threadIdx.x;
    if (i >= NN) return;
    int b = batch[i];
    float ratio = fminf(Bt[b] / (g_tot[b] + 1e-12f), 1.0f);
    out[i] = g_pi[i] * ratio;
}

extern "C" void kernel_launch(void* const* d_in, const int* in_sizes, int n_in,
                              void* d_out, int out_size) {
    const float* x      = (const float*)d_in[0];
    const int*   ei     = (const int*)d_in[1];
    const float* ea     = (const float*)d_in[2];
    const int*   batch  = (const int*)d_in[3];
    const float* Btot   = (const float*)d_in[4];
    const int*   tmask  = (const int*)d_in[5];
    const float* ccost  = (const float*)d_in[6];
    const float* e1w    = (const float*)d_in[7];
    const float* e1b    = (const float*)d_in[8];
    const float* w1a    = (const float*)d_in[9];
    const float* b1a    = (const float*)d_in[10];
    const float* w1b    = (const float*)d_in[11];
    const float* b1b    = (const float*)d_in[12];
    const float* e2w    = (const float*)d_in[13];
    const float* e2b    = (const float*)d_in[14];
    const float* w2a    = (const float*)d_in[15];
    const float* b2a    = (const float*)d_in[16];
    const float* w2b    = (const float*)d_in[17];
    const float* b2b    = (const float*)d_in[18];
    const float* wr1    = (const float*)d_in[19];
    const float* br1    = (const float*)d_in[20];
    const float* wr2    = (const float*)d_in[21];
    const float* br2    = (const float*)d_in[22];
    float* out = (float*)d_out;

    k_init<<<(NN + 255) / 256, 256>>>();
    k_prep<<<16, 256>>>(w1a, w1b, w2a, w2b, wr1);
    k_hist<<<(EE + 255) / 256, 256>>>(ei);
    k_scan1<<<NBLK_SCAN, 1024>>>();
    k_scan23<<<(NN + 255) / 256, 256>>>();
    k_scatter<<<(EE + 255) / 256, 256>>>(ei, ea);
    k_gather1<<<(NN + 7) / 8, 256>>>(x, e1w, e1b);
    k_mlp1<<<(NN + NPB - 1) / NPB, 256>>>(b1a, b1b);
    k_gather2<<<(NN + 7) / 8, 256>>>(e2w, e2b);
    k_mlp2<<<(NN + NPB - 1) / NPB, 256>>>(b2a, b2b);
    k_readout<<<782, 256>>>(br1, wr2, br2, batch, tmask, ccost);
    k_final<<<(NN + 255) / 256, 256>>>(batch, Btot, out);
}